// round 2
// baseline (speedup 1.0000x reference)
#include <cuda_runtime.h>
#include <math.h>

// FinancialPINN: Fourier-feature SIREN with residual blocks + periodic skips.
// Fully fused: one CTA processes a tile of 64 points through the entire
// network, keeping activations (transposed, [feature][point]) in shared
// memory and streaming each layer's weights into a shared 128x128 tile.
// Inner GEMM loops use packed fma.rn.f32x2 (FFMA2) for 2x fp32 throughput.

static constexpr int Fdim    = 128;   // Fourier features per trig fn
static constexpr int Hdim    = 128;   // hidden width
static constexpr int Ldim    = 8;     // residual blocks
static constexpr int MT      = 64;    // points per CTA
static constexpr int THREADS = 256;
static constexpr float OMEGA = 30.0f;

// shared layout (floats)
static constexpr int FF_OFF  = 0;                    // ff  [256][64]
static constexpr int XS_OFF  = FF_OFF + 2*Fdim*MT;   // Xs  [128][64]
static constexpr int HS_OFF  = XS_OFF + Hdim*MT;     // Hs  [128][64]
static constexpr int WS_OFF  = HS_OFF + Hdim*MT;     // Ws  [128][128]
static constexpr int SMEM_FLOATS = WS_OFF + Hdim*Hdim;  // 49152 floats = 192KB

typedef unsigned long long ull;

__device__ __forceinline__ ull pack2(float a) {
    ull r; asm("mov.b64 %0, {%1, %1};" : "=l"(r) : "f"(a)); return r;
}
__device__ __forceinline__ void unpack2(ull v, float& lo, float& hi) {
    asm("mov.b64 {%0, %1}, %2;" : "=f"(lo), "=f"(hi) : "l"(v));
}
__device__ __forceinline__ void fma2(ull& acc, ull x, ull w) {
    asm("fma.rn.f32x2 %0, %1, %2, %0;" : "+l"(acc) : "l"(x), "l"(w));
}

// Load a 128x128 f32 weight tile (contiguous in gmem) into Ws.
__device__ __forceinline__ void loadW(float* Ws, const float* __restrict__ g, int tid) {
    float4*       d = reinterpret_cast<float4*>(Ws);
    const float4* s = reinterpret_cast<const float4*>(g);
#pragma unroll
    for (int i = 0; i < 16; i++) d[tid + i * THREADS] = s[tid + i * THREADS];
}

// acc[mi][nj] (+)= A^T-tile @ W-tile.
// A: [K][MT] in smem (feature-major), W: [K][128] in smem.
// Thread (tx,ty): m = tx*4..tx*4+3, n = ty*8..ty*8+7 (as 4 packed pairs).
__device__ __forceinline__ void gemm_acc(const float* __restrict__ A,
                                         const float* __restrict__ W,
                                         int K, ull acc[4][4], int tx, int ty) {
    const float* a = A + tx * 4;
    const float* w = W + ty * 8;
#pragma unroll 8
    for (int k = 0; k < K; k++) {
        float4 xv = *reinterpret_cast<const float4*>(a);
        ulonglong2 w01 = *reinterpret_cast<const ulonglong2*>(w);
        ulonglong2 w23 = *reinterpret_cast<const ulonglong2*>(w + 4);
        a += MT;
        w += Hdim;
        ull xb0 = pack2(xv.x), xb1 = pack2(xv.y), xb2 = pack2(xv.z), xb3 = pack2(xv.w);
        ull wv0 = w01.x, wv1 = w01.y, wv2 = w23.x, wv3 = w23.y;
        fma2(acc[0][0], xb0, wv0); fma2(acc[0][1], xb0, wv1);
        fma2(acc[0][2], xb0, wv2); fma2(acc[0][3], xb0, wv3);
        fma2(acc[1][0], xb1, wv0); fma2(acc[1][1], xb1, wv1);
        fma2(acc[1][2], xb1, wv2); fma2(acc[1][3], xb1, wv3);
        fma2(acc[2][0], xb2, wv0); fma2(acc[2][1], xb2, wv1);
        fma2(acc[2][2], xb2, wv2); fma2(acc[2][3], xb2, wv3);
        fma2(acc[3][0], xb3, wv0); fma2(acc[3][1], xb3, wv1);
        fma2(acc[3][2], xb3, wv2); fma2(acc[3][3], xb3, wv3);
    }
}

__device__ __forceinline__ void zero_acc(ull acc[4][4]) {
#pragma unroll
    for (int i = 0; i < 4; i++)
#pragma unroll
        for (int j = 0; j < 4; j++) acc[i][j] = 0ULL;
}

extern __shared__ float smem[];

__global__ void __launch_bounds__(THREADS, 1)
pinn_kernel(const float* __restrict__ S,   const float* __restrict__ T,
            const float* __restrict__ B,
            const float* __restrict__ in_w, const float* __restrict__ in_b,
            const float* __restrict__ w1,   const float* __restrict__ b1,
            const float* __restrict__ w2,   const float* __restrict__ b2,
            const float* __restrict__ skw,  const float* __restrict__ skb,
            const float* __restrict__ ow,   const float* __restrict__ ob,
            float* __restrict__ out, int N) {
    float* ff = smem + FF_OFF;   // [2F][MT]
    float* Xs = smem + XS_OFF;   // [H][MT]
    float* Hs = smem + HS_OFF;   // [H][MT]
    float* Ws = smem + WS_OFF;   // [128][128]

    const int tid  = threadIdx.x;
    const int tx   = tid & 15;        // m direction
    const int ty   = tid >> 4;        // n direction
    const int mb   = tx * 4;
    const int nb   = ty * 8;
    const int base = blockIdx.x * MT;

    // ---- stage S,t for this tile into smem (reuse Hs as scratch) ----
    if (tid < MT) {
        int gm = base + tid;
        Hs[tid]      = (gm < N) ? S[gm] : 0.0f;
        Hs[MT + tid] = (gm < N) ? T[gm] : 0.0f;
    }
    __syncthreads();

    // ---- Fourier features: ff[f][m] = sin(proj), ff[F+f][m] = cos(proj) ----
#pragma unroll
    for (int i = 0; i < (2 * Fdim * MT / 2) / THREADS; i++) {   // 8192 (f,m) pairs / 256
        int e = tid + i * THREADS;
        int m = e & (MT - 1);
        int f = e >> 6;
        float proj = Hs[m] * B[f] + Hs[MT + m] * B[Fdim + f];
        float sn, cs;
        sincosf(proj, &sn, &cs);
        ff[f * MT + m]          = sn;
        ff[(f + Fdim) * MT + m] = cs;
    }
    __syncthreads();

    ull acc[4][4];

    // ---- input layer: x = sin(OMEGA * (ff @ in_w + in_b)), K = 256 ----
    zero_acc(acc);
    loadW(Ws, in_w, tid);
    __syncthreads();
    gemm_acc(ff, Ws, Fdim, acc, tx, ty);
    __syncthreads();
    loadW(Ws, in_w + Fdim * Hdim, tid);
    __syncthreads();
    gemm_acc(ff + Fdim * MT, Ws, Fdim, acc, tx, ty);
#pragma unroll
    for (int nj = 0; nj < 4; nj++) {
        float2 bb = *reinterpret_cast<const float2*>(in_b + nb + 2 * nj);
#pragma unroll
        for (int mi = 0; mi < 4; mi++) {
            float v0, v1; unpack2(acc[mi][nj], v0, v1);
            Xs[(nb + 2 * nj) * MT + mb + mi]     = sinf(OMEGA * (v0 + bb.x));
            Xs[(nb + 2 * nj + 1) * MT + mb + mi] = sinf(OMEGA * (v1 + bb.y));
        }
    }
    __syncthreads();

    // ---- residual blocks ----
    for (int layer = 0; layer < Ldim; layer++) {
        // h = tanh(x @ w1 + b1)
        loadW(Ws, w1 + layer * Hdim * Hdim, tid);
        __syncthreads();
        zero_acc(acc);
        gemm_acc(Xs, Ws, Hdim, acc, tx, ty);
#pragma unroll
        for (int nj = 0; nj < 4; nj++) {
            float2 bb = *reinterpret_cast<const float2*>(b1 + layer * Hdim + nb + 2 * nj);
#pragma unroll
            for (int mi = 0; mi < 4; mi++) {
                float v0, v1; unpack2(acc[mi][nj], v0, v1);
                Hs[(nb + 2 * nj) * MT + mb + mi]     = tanhf(v0 + bb.x);
                Hs[(nb + 2 * nj + 1) * MT + mb + mi] = tanhf(v1 + bb.y);
            }
        }
        __syncthreads();

        // acc = h @ w2   (b2 added at the end)
        loadW(Ws, w2 + layer * Hdim * Hdim, tid);
        __syncthreads();
        zero_acc(acc);
        gemm_acc(Hs, Ws, Hdim, acc, tx, ty);

        bool has_skip = ((layer & 1) == 0);
        if (has_skip) {
            // acc += ff @ skip_w[layer/2], K = 256 streamed as 2 chunks
            const float* sw = skw + (layer / 2) * (2 * Fdim) * Hdim;
            __syncthreads();               // gemm done reading Ws
            loadW(Ws, sw, tid);
            __syncthreads();
            gemm_acc(ff, Ws, Fdim, acc, tx, ty);
            __syncthreads();
            loadW(Ws, sw + Fdim * Hdim, tid);
            __syncthreads();
            gemm_acc(ff + Fdim * MT, Ws, Fdim, acc, tx, ty);
        }

        // x += acc + b2 (+ skip_b)
#pragma unroll
        for (int nj = 0; nj < 4; nj++) {
            float2 b2v = *reinterpret_cast<const float2*>(b2 + layer * Hdim + nb + 2 * nj);
            float2 sbv = make_float2(0.0f, 0.0f);
            if (has_skip)
                sbv = *reinterpret_cast<const float2*>(skb + (layer / 2) * Hdim + nb + 2 * nj);
#pragma unroll
            for (int mi = 0; mi < 4; mi++) {
                float v0, v1; unpack2(acc[mi][nj], v0, v1);
                Xs[(nb + 2 * nj) * MT + mb + mi]     += v0 + b2v.x + sbv.x;
                Xs[(nb + 2 * nj + 1) * MT + mb + mi] += v1 + b2v.y + sbv.y;
            }
        }
        __syncthreads();
    }

    // ---- output layer: out = x @ out_w + out_b ----
    if (tid < Hdim) Hs[tid] = ow[tid];     // Hs reused as out_w stage
    __syncthreads();
    if (tid < MT) {
        int gm = base + tid;
        if (gm < N) {
            float s = ob[0];
#pragma unroll 8
            for (int n = 0; n < Hdim; n++) s += Xs[n * MT + tid] * Hs[n];
            out[gm] = s;
        }
    }
}

extern "C" void kernel_launch(void* const* d_in, const int* in_sizes, int n_in,
                              void* d_out, int out_size) {
    const float* S    = (const float*)d_in[0];
    const float* T    = (const float*)d_in[1];
    const float* B    = (const float*)d_in[2];
    const float* in_w = (const float*)d_in[3];
    const float* in_b = (const float*)d_in[4];
    const float* w1   = (const float*)d_in[5];
    const float* b1   = (const float*)d_in[6];
    const float* w2   = (const float*)d_in[7];
    const float* b2   = (const float*)d_in[8];
    const float* skw  = (const float*)d_in[9];
    const float* skb  = (const float*)d_in[10];
    const float* ow   = (const float*)d_in[11];
    const float* ob   = (const float*)d_in[12];
    float* out        = (float*)d_out;

    int N = in_sizes[0];
    int grid = (N + MT - 1) / MT;
    size_t smem_bytes = SMEM_FLOATS * sizeof(float);

    cudaFuncSetAttribute(pinn_kernel, cudaFuncAttributeMaxDynamicSharedMemorySize,
                         (int)smem_bytes);
    pinn_kernel<<<grid, THREADS, smem_bytes>>>(S, T, B, in_w, in_b, w1, b1, w2, b2,
                                               skw, skb, ow, ob, out, N);
}